// round 9
// baseline (speedup 1.0000x reference)
#include <cuda_runtime.h>

// MFNet two-layer MFConv. Key facts exploited:
//  - indegree ~ Poisson(E/N=16) clamped to MAX_DEG=10 => ~96% of nodes in
//    bucket 10. For those, project-then-aggregate: gather 128B y10 rows
//    instead of 512B x rows (4x less L2 gather traffic).
//  - (W,Wr) interleaved as f32x2 pairs; fma.rn.f32x2 drives both matvecs.
//  - minority (deg<10) nodes compacted; handled by a wide-gather fallback.
// Replay-safety: ALL mutable __device__ state is re-initialized every launch
// with grids sized for N (the R7 bug was k_init's grid covering only 45K of
// 100K nodes -> stale degrees accumulated across graph replays -> OOB).

#define NMAX 100352
#define EMAX 1664000
#define FIN  128
#define FH   32
#define FO   64
#define DMAX 10
#define TPB  256
#define GRP  4

typedef unsigned long long u64;

// scratch (static __device__ — no allocations allowed)
__device__ int g_deg[NMAX];
__device__ int g_partial[1024];
__device__ int g_rowptr[NMAX + 1];
__device__ int g_cursor[NMAX];
__device__ int g_csr[EMAX];
__device__ int g_mcnt;
__device__ int g_mlist[NMAX];
__device__ __align__(16) float g_h[NMAX * FH];       // 12.8 MB
__device__ __align__(16) float g_y10[NMAX * FH];     // x @ W1[10]
__device__ __align__(16) float g_r10[NMAX * FH];     // x @ Wr1[10]
__device__ __align__(16) u64 g_Wp1[11 * FIN * FH];   // (W1,Wr1) interleaved
__device__ __align__(16) u64 g_Wp2[11 * FH * FO];    // (W2,Wr2) interleaved

__device__ __forceinline__ u64 pack2(float lo, float hi) {
    u64 r; asm("mov.b64 %0, {%1, %2};" : "=l"(r) : "f"(lo), "f"(hi)); return r;
}
__device__ __forceinline__ void unpack2(u64 v, float& lo, float& hi) {
    asm("mov.b64 {%0, %1}, %2;" : "=f"(lo), "=f"(hi) : "l"(v));
}
__device__ __forceinline__ void fma2(u64& d, u64 a, u64 b) {
    asm("fma.rn.f32x2 %0, %1, %2, %0;" : "+l"(d) : "l"(a), "l"(b));
}

// -------------------------------------------- init: zero deg + pack weights
// Grid MUST cover max(N, 11*FIN*FH) threads.
__global__ void k_init(const float* __restrict__ W1, const float* __restrict__ Wr1,
                       const float* __restrict__ W2, const float* __restrict__ Wr2,
                       int N) {
    int i = blockIdx.x * blockDim.x + threadIdx.x;
    if (i < N) g_deg[i] = 0;
    if (i == 0) g_mcnt = 0;
    if (i < 11 * FIN * FH) g_Wp1[i] = pack2(W1[i], Wr1[i]);
    if (i < 11 * FH * FO)  g_Wp2[i] = pack2(W2[i], Wr2[i]);
}

__global__ void k_hist(const int* __restrict__ ei, int E, int N) {
    int e = blockIdx.x * blockDim.x + threadIdx.x;
    if (e >= E) return;
    int d = __ldg(ei + E + e);
    if ((unsigned)d < (unsigned)N) atomicAdd(g_deg + d, 1);
}

// -------------------------------------------------------- 3-phase excl. scan
__global__ void k_blocksum(int N) {
    __shared__ int sh[TPB];
    int n = blockIdx.x * TPB + threadIdx.x;
    sh[threadIdx.x] = (n < N) ? g_deg[n] : 0;
    __syncthreads();
    for (int s = TPB / 2; s > 0; s >>= 1) {
        if (threadIdx.x < s) sh[threadIdx.x] += sh[threadIdx.x + s];
        __syncthreads();
    }
    if (threadIdx.x == 0) g_partial[blockIdx.x] = sh[0];
}
__global__ void k_scanpartial(int nb) {
    __shared__ int sh[1024];
    int i = threadIdx.x;
    int v = (i < nb) ? g_partial[i] : 0;
    sh[i] = v;
    __syncthreads();
    for (int off = 1; off < 1024; off <<= 1) {
        int t = (i >= off) ? sh[i - off] : 0;
        __syncthreads();
        sh[i] += t;
        __syncthreads();
    }
    if (i < nb) g_partial[i] = sh[i] - v;
}
__global__ void k_writeptr(int N, int E) {
    __shared__ int sh[TPB];
    int n = blockIdx.x * TPB + threadIdx.x;
    int v = (n < N) ? g_deg[n] : 0;
    sh[threadIdx.x] = v;
    __syncthreads();
    for (int off = 1; off < TPB; off <<= 1) {
        int t = (threadIdx.x >= off) ? sh[threadIdx.x - off] : 0;
        __syncthreads();
        sh[threadIdx.x] += t;
        __syncthreads();
    }
    int excl = sh[threadIdx.x] - v + g_partial[blockIdx.x];
    if (n < N) {
        g_rowptr[n] = excl;
        g_cursor[n] = excl;
        if (v < DMAX) g_mlist[atomicAdd(&g_mcnt, 1)] = n;  // minority nodes
    }
    if (n == 0) g_rowptr[N] = E;
}
__global__ void k_place(const int* __restrict__ ei, int E, int N) {
    int e = blockIdx.x * blockDim.x + threadIdx.x;
    if (e >= E) return;
    int s = __ldg(ei + e);
    int d = __ldg(ei + E + e);
    if ((unsigned)s >= (unsigned)N || (unsigned)d >= (unsigned)N) return;
    int pos = atomicAdd(g_cursor + d, 1);
    if (pos < EMAX) g_csr[pos] = s;
}

// ---------------------- pre-projection: y10 = x@W1[10], r10 = x@Wr1[10]
__global__ __launch_bounds__(TPB) void k_proj1(const float* __restrict__ x, int N) {
    __shared__ u64 sh[TPB / 32][GRP * FIN];   // 8 warps x 4KB
    int gw = (blockIdx.x * blockDim.x + threadIdx.x) >> 5;
    int lane = threadIdx.x & 31;
    u64* hx = sh[threadIdx.x >> 5];
    int base = gw * GRP;
    if (base >= N) return;

#pragma unroll
    for (int g = 0; g < GRP; g++) {
        int n = base + g;
        float4 v = make_float4(0.f, 0.f, 0.f, 0.f);
        if (n < N) v = *reinterpret_cast<const float4*>(x + (size_t)n * FIN + lane * 4);
        hx[g * FIN + 4 * lane + 0] = pack2(v.x, v.x);
        hx[g * FIN + 4 * lane + 1] = pack2(v.y, v.y);
        hx[g * FIN + 4 * lane + 2] = pack2(v.z, v.z);
        hx[g * FIN + 4 * lane + 3] = pack2(v.w, v.w);
    }
    __syncwarp();

    u64 acc[GRP];
#pragma unroll
    for (int g = 0; g < GRP; g++) acc[g] = 0ull;

    const u64* Wp = g_Wp1 + DMAX * FIN * FH;
#pragma unroll 8
    for (int f = 0; f < FIN; f++) {
        u64 wv = __ldg(Wp + f * FH + lane);
        fma2(acc[0], hx[0 * FIN + f], wv);
        fma2(acc[1], hx[1 * FIN + f], wv);
        fma2(acc[2], hx[2 * FIN + f], wv);
        fma2(acc[3], hx[3 * FIN + f], wv);
    }
#pragma unroll
    for (int g = 0; g < GRP; g++) {
        int n = base + g;
        if (n < N) {
            float y, r; unpack2(acc[g], y, r);
            g_y10[(size_t)n * FH + lane] = y;
            g_r10[(size_t)n * FH + lane] = r;
        }
    }
}

// ----------------- majority aggregation (deg>=10): gather 128B y10 rows
__global__ __launch_bounds__(TPB) void k_agg1(const float* __restrict__ b1, int N) {
    int t = blockIdx.x * blockDim.x + threadIdx.x;
    int n = t >> 5, lane = t & 31;
    if (n >= N) return;
    int beg = g_rowptr[n], end = g_rowptr[n + 1];
    if (end - beg < DMAX) return;            // minority handled elsewhere
    float hs = 0.f;
#pragma unroll 4
    for (int j = beg; j < end; j++) {
        int s = __ldg(g_csr + j);
        hs += __ldg(g_y10 + (size_t)s * FH + lane);
    }
    hs += __ldg(b1 + DMAX * FH + lane) + g_r10[(size_t)n * FH + lane];
    g_h[(size_t)n * FH + lane] = fmaxf(hs, 0.f);
}

// -------------- minority (deg<10): wide gather of x + per-bucket matvec
__global__ __launch_bounds__(TPB) void k_minor1(const float* __restrict__ x,
                                                const float* __restrict__ b1) {
    int gw = (blockIdx.x * blockDim.x + threadIdx.x) >> 5;
    int lane = threadIdx.x & 31;
    if (gw >= g_mcnt) return;
    int n = g_mlist[gw];
    int beg = g_rowptr[n], end = g_rowptr[n + 1];
    int d = min(end - beg, DMAX);

    float a0 = 0.f, a1 = 0.f, a2 = 0.f, a3 = 0.f;
    for (int j = beg; j < end; j++) {
        int s = __ldg(g_csr + j);
        float4 v = *reinterpret_cast<const float4*>(x + (size_t)s * FIN + lane * 4);
        a0 += v.x; a1 += v.y; a2 += v.z; a3 += v.w;
    }
    float4 xr = *reinterpret_cast<const float4*>(x + (size_t)n * FIN + lane * 4);

    const u64* Wp = g_Wp1 + d * FIN * FH;
    u64 acc = pack2(__ldg(b1 + d * FH + lane), 0.f);
#pragma unroll
    for (int q = 0; q < 32; q++) {
        float h0 = __shfl_sync(0xffffffffu, a0, q);
        float h1 = __shfl_sync(0xffffffffu, a1, q);
        float h2 = __shfl_sync(0xffffffffu, a2, q);
        float h3 = __shfl_sync(0xffffffffu, a3, q);
        float x0 = __shfl_sync(0xffffffffu, xr.x, q);
        float x1 = __shfl_sync(0xffffffffu, xr.y, q);
        float x2 = __shfl_sync(0xffffffffu, xr.z, q);
        float x3 = __shfl_sync(0xffffffffu, xr.w, q);
        int f = q * 4;
        fma2(acc, pack2(h0, x0), __ldg(Wp + (f + 0) * FH + lane));
        fma2(acc, pack2(h1, x1), __ldg(Wp + (f + 1) * FH + lane));
        fma2(acc, pack2(h2, x2), __ldg(Wp + (f + 2) * FH + lane));
        fma2(acc, pack2(h3, x3), __ldg(Wp + (f + 3) * FH + lane));
    }
    float lo, hi; unpack2(acc, lo, hi);
    g_h[(size_t)n * FH + lane] = fmaxf(lo + hi, 0.f);
}

// --------------------------------------- layer 2: fused gather + transform
__global__ __launch_bounds__(TPB) void k_fused2(const float* __restrict__ b2,
                                                float* __restrict__ out, int N) {
    __shared__ u64 sh[TPB / 32][GRP * FH];
    int gw = (blockIdx.x * blockDim.x + threadIdx.x) >> 5;
    int lane = threadIdx.x & 31;
    u64* hh = sh[threadIdx.x >> 5];
    int base = gw * GRP;
    if (base >= N) return;

    int dg[GRP];
#pragma unroll
    for (int g = 0; g < GRP; g++) {
        int n = base + g;
        float hs = 0.f, hn = 0.f;
        int d = 0;
        if (n < N) {
            int beg = g_rowptr[n], end = g_rowptr[n + 1];
            d = min(end - beg, DMAX);
#pragma unroll 2
            for (int j = beg; j < end; j++) {
                int s = __ldg(g_csr + j);
                hs += g_h[(size_t)s * FH + lane];
            }
            hn = g_h[(size_t)n * FH + lane];
        }
        dg[g] = d;
        hh[g * FH + lane] = pack2(hs, hn);
    }
    __syncwarp();

    u64 acc0[GRP], acc1[GRP];
#pragma unroll
    for (int g = 0; g < GRP; g++) {
        acc0[g] = pack2(__ldg(b2 + dg[g] * FO + lane), 0.f);
        acc1[g] = pack2(__ldg(b2 + dg[g] * FO + 32 + lane), 0.f);
    }

    if (dg[0] == dg[1] && dg[1] == dg[2] && dg[2] == dg[3]) {
        const u64* Wp = g_Wp2 + dg[0] * FH * FO;
#pragma unroll 8
        for (int j = 0; j < FH; j++) {
            u64 w0 = __ldg(Wp + j * FO + lane);
            u64 w1 = __ldg(Wp + j * FO + 32 + lane);
#pragma unroll
            for (int g = 0; g < GRP; g++) {
                u64 hv = hh[g * FH + j];
                fma2(acc0[g], hv, w0);
                fma2(acc1[g], hv, w1);
            }
        }
    } else {
#pragma unroll
        for (int g = 0; g < GRP; g++) {
            const u64* Wp = g_Wp2 + dg[g] * FH * FO;
#pragma unroll 8
            for (int j = 0; j < FH; j++) {
                u64 hv = hh[g * FH + j];
                fma2(acc0[g], hv, __ldg(Wp + j * FO + lane));
                fma2(acc1[g], hv, __ldg(Wp + j * FO + 32 + lane));
            }
        }
    }
#pragma unroll
    for (int g = 0; g < GRP; g++) {
        int n = base + g;
        if (n < N) {
            float lo, hi;
            unpack2(acc0[g], lo, hi);
            out[(size_t)n * FO + lane] = lo + hi;
            unpack2(acc1[g], lo, hi);
            out[(size_t)n * FO + 32 + lane] = lo + hi;
        }
    }
}

// ============================================================================
extern "C" void kernel_launch(void* const* d_in, const int* in_sizes, int n_in,
                              void* d_out, int out_size) {
    const float* x   = (const float*)d_in[0];
    const int*   ei  = (const int*)d_in[1];     // int32 (JAX x64 disabled)
    const float* W1  = (const float*)d_in[2];
    const float* b1  = (const float*)d_in[3];
    const float* Wr1 = (const float*)d_in[4];
    const float* W2  = (const float*)d_in[5];
    const float* b2  = (const float*)d_in[6];
    const float* Wr2 = (const float*)d_in[7];
    float* out = (float*)d_out;

    int N = in_sizes[0] / FIN;
    int E = in_sizes[1] / 2;
    if (N > NMAX) N = NMAX;
    if (E > EMAX) E = EMAX;

    int nb = (N + TPB - 1) / TPB;
    int egrid = (E + TPB - 1) / TPB;
    int nwarps = (N + GRP - 1) / GRP;
    int fgrid = (nwarps * 32 + TPB - 1) / TPB;
    int wgrid = (N * 32 + TPB - 1) / TPB;

    // init grid must cover BOTH the weight tables and all N nodes
    int initthreads = 11 * FIN * FH;
    if (N > initthreads) initthreads = N;
    k_init<<<(initthreads + TPB - 1) / TPB, TPB>>>(W1, Wr1, W2, Wr2, N);
    k_hist<<<egrid, TPB>>>(ei, E, N);
    k_blocksum<<<nb, TPB>>>(N);
    k_scanpartial<<<1, 1024>>>(nb);
    k_writeptr<<<nb, TPB>>>(N, E);
    k_place<<<egrid, TPB>>>(ei, E, N);
    k_proj1<<<fgrid, TPB>>>(x, N);
    k_agg1<<<wgrid, TPB>>>(b1, N);
    k_minor1<<<wgrid, TPB>>>(x, b1);
    k_fused2<<<fgrid, TPB>>>(b2, out, N);
}

// round 10
// speedup vs baseline: 1.4454x; 1.4454x over previous
#include <cuda_runtime.h>

// MFNet two-layer MFConv — R5 structure (best known), minus the prefix scan.
//   CSR slice allocation via warp-aggregated atomicAdd (node order irrelevant).
//   5 launches: hist, alloc+pack, place(+deg restore), fused1, fused2(+total
//   restore). Replay-safe: every mutable global is either rewritten before use
//   this run or restored to its BSS-zero entry state by a later kernel.
//   (W,Wr) interleaved as f32x2; fma.rn.f32x2 drives both matvecs at once.

#define NMAX 100352
#define EMAX 1664000
#define FIN  128
#define FH   32
#define FO   64
#define DMAX 10
#define TPB  256
#define GRP  4
#define NW1  (11 * FIN * FH)   // 45056
#define NW2  (11 * FH * FO)    // 22528

typedef unsigned long long u64;

// scratch (static __device__ — no allocations allowed)
__device__ int g_deg[NMAX];      // INVARIANT: zero at kernel_launch entry
__device__ int g_total;          // INVARIANT: zero at kernel_launch entry
__device__ int g_rowbeg[NMAX];
__device__ int g_rowend[NMAX];
__device__ int g_cursor[NMAX];
__device__ int g_csr[EMAX];
__device__ __align__(16) float g_h[NMAX * FH];     // 12.8 MB
__device__ __align__(16) u64 g_Wp1[NW1];           // (W1,Wr1) interleaved
__device__ __align__(16) u64 g_Wp2[NW2];           // (W2,Wr2) interleaved

__device__ __forceinline__ u64 pack2(float lo, float hi) {
    u64 r; asm("mov.b64 %0, {%1, %2};" : "=l"(r) : "f"(lo), "f"(hi)); return r;
}
__device__ __forceinline__ void unpack2(u64 v, float& lo, float& hi) {
    asm("mov.b64 {%0, %1}, %2;" : "=f"(lo), "=f"(hi) : "l"(v));
}
__device__ __forceinline__ void fma2(u64& d, u64 a, u64 b) {
    asm("fma.rn.f32x2 %0, %1, %2, %0;" : "+l"(d) : "l"(a), "l"(b));
}

// ------------------------------------------- [0] degree histogram (deg==0 in)
__global__ void k_hist(const int* __restrict__ ei, int E, int N) {
    int e = blockIdx.x * blockDim.x + threadIdx.x;
    if (e >= E) return;
    int d = __ldg(ei + E + e);
    if ((unsigned)d < (unsigned)N) atomicAdd(g_deg + d, 1);
}

// ---------------- [1] slice allocation (warp-aggregated atomic) + weight pack
__global__ void k_alloc(const float* __restrict__ W1, const float* __restrict__ Wr1,
                        const float* __restrict__ W2, const float* __restrict__ Wr2,
                        int N) {
    int i = blockIdx.x * blockDim.x + threadIdx.x;
    if (i < NW1) g_Wp1[i] = pack2(__ldg(W1 + i), __ldg(Wr1 + i));
    if (i < NW2) g_Wp2[i] = pack2(__ldg(W2 + i), __ldg(Wr2 + i));

    int lane = threadIdx.x & 31;
    int d = (i < N) ? g_deg[i] : 0;
    int incl = d;
#pragma unroll
    for (int off = 1; off < 32; off <<= 1) {
        int v = __shfl_up_sync(0xffffffffu, incl, off);
        if (lane >= off) incl += v;
    }
    int wtot = __shfl_sync(0xffffffffu, incl, 31);
    int base = 0;
    if (lane == 31) base = atomicAdd(&g_total, wtot);
    base = __shfl_sync(0xffffffffu, base, 31);
    int beg = base + incl - d;
    if (i < N) { g_rowbeg[i] = beg; g_rowend[i] = beg + d; g_cursor[i] = beg; }
}

// ---------------------- [2] CSR placement; restores g_deg=0 entry invariant
__global__ void k_place(const int* __restrict__ ei, int E, int N) {
    int e = blockIdx.x * blockDim.x + threadIdx.x;
    if (e < N) g_deg[e] = 0;                 // deg consumed by k_alloc; restore
    if (e >= E) return;
    int s = __ldg(ei + e);
    int d = __ldg(ei + E + e);
    if ((unsigned)s >= (unsigned)N || (unsigned)d >= (unsigned)N) return;
    int pos = atomicAdd(g_cursor + d, 1);
    if (pos < EMAX) g_csr[pos] = s;
}

// -------------------- [3] layer 1: fused gather + transform  (PROFILED SLOT)
// Warp handles 4 nodes. Gather: lane owns features [4L,4L+4); chunk-of-4 index
// prefetch makes the 4 row loads independent (MLP 4). (sum,x) staged packed in
// smem; matvec: lane = out channel, one LDG.64 + 4 LDS + 4 FFMA2 per feature.
__global__ __launch_bounds__(TPB) void k_fused1(const float* __restrict__ x,
                                                const float* __restrict__ b1, int N) {
    __shared__ u64 sh[TPB / 32][GRP * FIN];  // 8 warps x 4KB = 32KB
    int gw = (blockIdx.x * blockDim.x + threadIdx.x) >> 5;
    int lane = threadIdx.x & 31;
    u64* hx = sh[threadIdx.x >> 5];
    int base = gw * GRP;
    if (base >= N) return;

    int dg[GRP];
#pragma unroll
    for (int g = 0; g < GRP; g++) {
        int n = base + g;
        float a0 = 0.f, a1 = 0.f, a2 = 0.f, a3 = 0.f;
        float4 xr = make_float4(0.f, 0.f, 0.f, 0.f);
        int d = 0;
        if (n < N) {
            int beg = g_rowbeg[n], end = g_rowend[n];
            d = min(end - beg, DMAX);
            int j = beg;
            for (; j + 4 <= end; j += 4) {
                int s0 = __ldg(g_csr + j + 0);
                int s1 = __ldg(g_csr + j + 1);
                int s2 = __ldg(g_csr + j + 2);
                int s3 = __ldg(g_csr + j + 3);
                float4 v0 = *reinterpret_cast<const float4*>(x + (size_t)s0 * FIN + lane * 4);
                float4 v1 = *reinterpret_cast<const float4*>(x + (size_t)s1 * FIN + lane * 4);
                float4 v2 = *reinterpret_cast<const float4*>(x + (size_t)s2 * FIN + lane * 4);
                float4 v3 = *reinterpret_cast<const float4*>(x + (size_t)s3 * FIN + lane * 4);
                a0 += v0.x + v1.x + v2.x + v3.x;
                a1 += v0.y + v1.y + v2.y + v3.y;
                a2 += v0.z + v1.z + v2.z + v3.z;
                a3 += v0.w + v1.w + v2.w + v3.w;
            }
            for (; j < end; j++) {
                int s = __ldg(g_csr + j);
                float4 v = *reinterpret_cast<const float4*>(x + (size_t)s * FIN + lane * 4);
                a0 += v.x; a1 += v.y; a2 += v.z; a3 += v.w;
            }
            xr = *reinterpret_cast<const float4*>(x + (size_t)n * FIN + lane * 4);
        }
        dg[g] = d;
        hx[g * FIN + 4 * lane + 0] = pack2(a0, xr.x);
        hx[g * FIN + 4 * lane + 1] = pack2(a1, xr.y);
        hx[g * FIN + 4 * lane + 2] = pack2(a2, xr.z);
        hx[g * FIN + 4 * lane + 3] = pack2(a3, xr.w);
    }
    __syncwarp();

    u64 acc[GRP];
#pragma unroll
    for (int g = 0; g < GRP; g++)
        acc[g] = pack2(__ldg(b1 + dg[g] * FH + lane), 0.f);

    if (dg[0] == dg[1] && dg[1] == dg[2] && dg[2] == dg[3]) {
        const u64* Wp = g_Wp1 + dg[0] * FIN * FH;
#pragma unroll 8
        for (int f = 0; f < FIN; f++) {
            u64 wv = __ldg(Wp + f * FH + lane);
            fma2(acc[0], hx[0 * FIN + f], wv);
            fma2(acc[1], hx[1 * FIN + f], wv);
            fma2(acc[2], hx[2 * FIN + f], wv);
            fma2(acc[3], hx[3 * FIN + f], wv);
        }
    } else {
#pragma unroll
        for (int g = 0; g < GRP; g++) {
            const u64* Wp = g_Wp1 + dg[g] * FIN * FH;
#pragma unroll 8
            for (int f = 0; f < FIN; f++)
                fma2(acc[g], hx[g * FIN + f], __ldg(Wp + f * FH + lane));
        }
    }
#pragma unroll
    for (int g = 0; g < GRP; g++) {
        int n = base + g;
        if (n < N) {
            float lo, hi; unpack2(acc[g], lo, hi);
            g_h[(size_t)n * FH + lane] = fmaxf(lo + hi, 0.f);
        }
    }
}

// ------------- [4] layer 2: fused gather + transform; restores g_total=0
__global__ __launch_bounds__(TPB) void k_fused2(const float* __restrict__ b2,
                                                float* __restrict__ out, int N) {
    if (blockIdx.x == 0 && threadIdx.x == 0) g_total = 0;  // restore invariant
    __shared__ u64 sh[TPB / 32][GRP * FH];
    int gw = (blockIdx.x * blockDim.x + threadIdx.x) >> 5;
    int lane = threadIdx.x & 31;
    u64* hh = sh[threadIdx.x >> 5];
    int base = gw * GRP;
    if (base >= N) return;

    int dg[GRP];
#pragma unroll
    for (int g = 0; g < GRP; g++) {
        int n = base + g;
        float hs = 0.f, hn = 0.f;
        int d = 0;
        if (n < N) {
            int beg = g_rowbeg[n], end = g_rowend[n];
            d = min(end - beg, DMAX);
            int j = beg;
            for (; j + 4 <= end; j += 4) {
                int s0 = __ldg(g_csr + j + 0);
                int s1 = __ldg(g_csr + j + 1);
                int s2 = __ldg(g_csr + j + 2);
                int s3 = __ldg(g_csr + j + 3);
                hs += g_h[(size_t)s0 * FH + lane] + g_h[(size_t)s1 * FH + lane]
                    + g_h[(size_t)s2 * FH + lane] + g_h[(size_t)s3 * FH + lane];
            }
            for (; j < end; j++) {
                int s = __ldg(g_csr + j);
                hs += g_h[(size_t)s * FH + lane];
            }
            hn = g_h[(size_t)n * FH + lane];
        }
        dg[g] = d;
        hh[g * FH + lane] = pack2(hs, hn);
    }
    __syncwarp();

    u64 acc0[GRP], acc1[GRP];
#pragma unroll
    for (int g = 0; g < GRP; g++) {
        acc0[g] = pack2(__ldg(b2 + dg[g] * FO + lane), 0.f);
        acc1[g] = pack2(__ldg(b2 + dg[g] * FO + 32 + lane), 0.f);
    }

    if (dg[0] == dg[1] && dg[1] == dg[2] && dg[2] == dg[3]) {
        const u64* Wp = g_Wp2 + dg[0] * FH * FO;
#pragma unroll 8
        for (int j = 0; j < FH; j++) {
            u64 w0 = __ldg(Wp + j * FO + lane);
            u64 w1 = __ldg(Wp + j * FO + 32 + lane);
#pragma unroll
            for (int g = 0; g < GRP; g++) {
                u64 hv = hh[g * FH + j];
                fma2(acc0[g], hv, w0);
                fma2(acc1[g], hv, w1);
            }
        }
    } else {
#pragma unroll
        for (int g = 0; g < GRP; g++) {
            const u64* Wp = g_Wp2 + dg[g] * FH * FO;
#pragma unroll 8
            for (int j = 0; j < FH; j++) {
                u64 hv = hh[g * FH + j];
                fma2(acc0[g], hv, __ldg(Wp + j * FO + lane));
                fma2(acc1[g], hv, __ldg(Wp + j * FO + 32 + lane));
            }
        }
    }
#pragma unroll
    for (int g = 0; g < GRP; g++) {
        int n = base + g;
        if (n < N) {
            float lo, hi;
            unpack2(acc0[g], lo, hi);
            out[(size_t)n * FO + lane] = lo + hi;
            unpack2(acc1[g], lo, hi);
            out[(size_t)n * FO + 32 + lane] = lo + hi;
        }
    }
}

// ============================================================================
extern "C" void kernel_launch(void* const* d_in, const int* in_sizes, int n_in,
                              void* d_out, int out_size) {
    const float* x   = (const float*)d_in[0];
    const int*   ei  = (const int*)d_in[1];     // int32 (JAX x64 disabled)
    const float* W1  = (const float*)d_in[2];
    const float* b1  = (const float*)d_in[3];
    const float* Wr1 = (const float*)d_in[4];
    const float* W2  = (const float*)d_in[5];
    const float* b2  = (const float*)d_in[6];
    const float* Wr2 = (const float*)d_in[7];
    float* out = (float*)d_out;

    int N = in_sizes[0] / FIN;
    int E = in_sizes[1] / 2;
    if (N > NMAX) N = NMAX;
    if (E > EMAX) E = EMAX;

    int nb    = (N + TPB - 1) / TPB;           // 391 (covers NW1=45056 too)
    int egrid = (E + TPB - 1) / TPB;
    int nwarps = (N + GRP - 1) / GRP;
    int fgrid = (nwarps * 32 + TPB - 1) / TPB;

    k_hist <<<egrid, TPB>>>(ei, E, N);                 // launch 0
    k_alloc<<<nb,    TPB>>>(W1, Wr1, W2, Wr2, N);      // launch 1
    k_place<<<egrid, TPB>>>(ei, E, N);                 // launch 2
    k_fused1<<<fgrid, TPB>>>(x, b1, N);                // launch 3  <- profiled
    k_fused2<<<fgrid, TPB>>>(b2, out, N);              // launch 4
}